// round 4
// baseline (speedup 1.0000x reference)
#include <cuda_runtime.h>
#include <cuda_bf16.h>
#include <cstdint>
#include <cstddef>

#define HID   1024
#define BATCH 256
#define SEQ   512
#define VOCAB 32000
#define G3    3072   // 3*HID

// persistent-scan geometry
#define NCTA  128
#define UNITS 16          // hidden units per CTA
#define NROWS 48          // 3 gates * UNITS
#define MCTA  128         // batch rows per CTA
#define WST   1032        // smem W stride (bf16), conflict-free
#define AST   24          // smem A stride (bf16), conflict-free
#define KC    16          // k-tile
#define KT    (HID / KC)  // 64

// dynamic smem layout (bytes)
#define OFF_WHI 0
#define OFF_WLO (NROWS * WST * 2)            // 99072
#define OFF_REG (2 * NROWS * WST * 2)        // 198144
#define A_PLANE (MCTA * AST * 2)             // 6144
#define HG_STRIDE 51
#define REG_BYTES 26112                       // max(4*A_PLANE=24576, 128*51*4=26112)
#define SMEM_TOTAL (OFF_REG + REG_BYTES)     // 224256

// ---------------- persistent scratch ----------------
__device__ __nv_bfloat16 g_Wih_hi[G3 * HID];
__device__ __nv_bfloat16 g_Wih_lo[G3 * HID];
__device__ __nv_bfloat16 g_Whh_hi[G3 * HID];
__device__ __nv_bfloat16 g_Whh_lo[G3 * HID];
__device__ float         g_E[(size_t)VOCAB * G3];   // emb @ W_ih^T
__device__ float         g_h0[BATCH * HID];
__device__ float         g_h1[BATCH * HID];
__device__ unsigned      g_count = 0;
__device__ unsigned      g_phase = 0;

// ---------------- helpers ----------------
__device__ __forceinline__ void split2(float x, __nv_bfloat16 &hi, __nv_bfloat16 &lo) {
    hi = __float2bfloat16_rn(x);
    lo = __float2bfloat16_rn(x - __bfloat162float(hi));
}
__device__ __forceinline__ unsigned pk(__nv_bfloat16 a, __nv_bfloat16 b) {
    return (unsigned)__bfloat16_as_ushort(a) | ((unsigned)__bfloat16_as_ushort(b) << 16);
}
__device__ __forceinline__ void mma16816(float *d, const unsigned *a, const unsigned *b) {
    asm volatile(
        "mma.sync.aligned.m16n8k16.row.col.f32.bf16.bf16.f32 "
        "{%0,%1,%2,%3},{%4,%5,%6,%7},{%8,%9},{%0,%1,%2,%3};\n"
        : "+f"(d[0]), "+f"(d[1]), "+f"(d[2]), "+f"(d[3])
        : "r"(a[0]), "r"(a[1]), "r"(a[2]), "r"(a[3]), "r"(b[0]), "r"(b[1]));
}
__device__ __forceinline__ float sigf(float x) { return 1.0f / (1.0f + __expf(-x)); }

// Grid barrier, hang-proofed: bounded spin so a residency failure degrades to a
// wrong answer + finite runtime instead of a container-killing infinite hang.
__device__ __forceinline__ void grid_bar(unsigned target) {
    __threadfence();
    __syncthreads();
    if (threadIdx.x == 0) {
        unsigned a = atomicAdd(&g_count, 1u);
        if (a == NCTA - 1) {
            g_count = 0;
            __threadfence();
            atomicExch(&g_phase, target);
        } else {
            for (int spin = 0; spin < 1000000; ++spin) {
                if (atomicAdd(&g_phase, 0u) == target) break;
                __nanosleep(64);
            }
        }
        __threadfence();   // acquire: order peer h writes before our reads
    }
    __syncthreads();
}

// ---------------- kernel: split weights into bf16 hi/lo ----------------
__global__ void k_split(const float *__restrict__ Wih, const float *__restrict__ Whh) {
    int i = blockIdx.x * blockDim.x + threadIdx.x;
    const int N = G3 * HID;
    if (i < N) {
        split2(Wih[i], g_Wih_hi[i], g_Wih_lo[i]);
    } else {
        int j = i - N;
        split2(Whh[j], g_Whh_hi[j], g_Whh_lo[j]);
    }
}

// ---------------- kernel: E = emb @ W_ih^T  (M=32000, N=3072, K=1024) ----------------
__global__ __launch_bounds__(256) void k_vocab(const float *__restrict__ emb) {
    __shared__ __nv_bfloat16 sA_hi[128 * 40];
    __shared__ __nv_bfloat16 sA_lo[128 * 40];
    __shared__ __nv_bfloat16 sB_hi[128 * 40];
    __shared__ __nv_bfloat16 sB_lo[128 * 40];

    const int tid = threadIdx.x;
    const int lane = tid & 31, warp = tid >> 5;
    const int wm = warp & 1, wn = warp >> 1;
    const int m0 = blockIdx.y * 128, n0 = blockIdx.x * 128;

    float acc[4][4][4] = {};
    const int g  = lane >> 2;
    const int c2 = (lane & 3) * 2;

    for (int kt = 0; kt < 32; ++kt) {
        const int k0 = kt * 32;
        __syncthreads();
        {
            const int r_ = tid >> 3, c4 = (tid & 7) * 4;
#pragma unroll
            for (int i = 0; i < 4; i++) {
                const int row = r_ + i * 32;
                float4 v = *reinterpret_cast<const float4 *>(
                    &emb[(size_t)(m0 + row) * HID + k0 + c4]);
                __nv_bfloat16 h0, h1, h2, h3, l0, l1, l2, l3;
                split2(v.x, h0, l0); split2(v.y, h1, l1);
                split2(v.z, h2, l2); split2(v.w, h3, l3);
                unsigned *ph = reinterpret_cast<unsigned *>(&sA_hi[row * 40 + c4]);
                ph[0] = pk(h0, h1); ph[1] = pk(h2, h3);
                unsigned *pl = reinterpret_cast<unsigned *>(&sA_lo[row * 40 + c4]);
                pl[0] = pk(l0, l1); pl[1] = pk(l2, l3);
            }
        }
        {
            const int rb = tid >> 2, q = tid & 3;
#pragma unroll
            for (int i = 0; i < 2; i++) {
                const int row = rb + i * 64;
                *reinterpret_cast<uint4 *>(&sB_hi[row * 40 + q * 8]) =
                    *reinterpret_cast<const uint4 *>(&g_Wih_hi[(size_t)(n0 + row) * HID + k0 + q * 8]);
                *reinterpret_cast<uint4 *>(&sB_lo[row * 40 + q * 8]) =
                    *reinterpret_cast<const uint4 *>(&g_Wih_lo[(size_t)(n0 + row) * HID + k0 + q * 8]);
            }
        }
        __syncthreads();

#pragma unroll
        for (int kk = 0; kk < 32; kk += 16) {
            unsigned ah[4][4], al[4][4];
#pragma unroll
            for (int mf = 0; mf < 4; mf++) {
                const int ra = wm * 64 + mf * 16 + g;
                ah[mf][0] = *reinterpret_cast<unsigned *>(&sA_hi[ra * 40 + kk + c2]);
                ah[mf][1] = *reinterpret_cast<unsigned *>(&sA_hi[(ra + 8) * 40 + kk + c2]);
                ah[mf][2] = *reinterpret_cast<unsigned *>(&sA_hi[ra * 40 + kk + c2 + 8]);
                ah[mf][3] = *reinterpret_cast<unsigned *>(&sA_hi[(ra + 8) * 40 + kk + c2 + 8]);
                al[mf][0] = *reinterpret_cast<unsigned *>(&sA_lo[ra * 40 + kk + c2]);
                al[mf][1] = *reinterpret_cast<unsigned *>(&sA_lo[(ra + 8) * 40 + kk + c2]);
                al[mf][2] = *reinterpret_cast<unsigned *>(&sA_lo[ra * 40 + kk + c2 + 8]);
                al[mf][3] = *reinterpret_cast<unsigned *>(&sA_lo[(ra + 8) * 40 + kk + c2 + 8]);
            }
#pragma unroll
            for (int nf = 0; nf < 4; nf++) {
                const int rb_ = wn * 32 + nf * 8 + g;
                unsigned bh[2], bl[2];
                bh[0] = *reinterpret_cast<unsigned *>(&sB_hi[rb_ * 40 + kk + c2]);
                bh[1] = *reinterpret_cast<unsigned *>(&sB_hi[rb_ * 40 + kk + c2 + 8]);
                bl[0] = *reinterpret_cast<unsigned *>(&sB_lo[rb_ * 40 + kk + c2]);
                bl[1] = *reinterpret_cast<unsigned *>(&sB_lo[rb_ * 40 + kk + c2 + 8]);
#pragma unroll
                for (int mf = 0; mf < 4; mf++) {
                    mma16816(acc[mf][nf], ah[mf], bh);
                    mma16816(acc[mf][nf], ah[mf], bl);
                    mma16816(acc[mf][nf], al[mf], bh);
                }
            }
        }
    }

#pragma unroll
    for (int mf = 0; mf < 4; mf++) {
#pragma unroll
        for (int nf = 0; nf < 4; nf++) {
            const int row = m0 + wm * 64 + mf * 16 + g;
            const int col = n0 + wn * 32 + nf * 8 + c2;
            *reinterpret_cast<float2 *>(&g_E[(size_t)row * G3 + col]) =
                make_float2(acc[mf][nf][0], acc[mf][nf][1]);
            *reinterpret_cast<float2 *>(&g_E[(size_t)(row + 8) * G3 + col]) =
                make_float2(acc[mf][nf][2], acc[mf][nf][3]);
        }
    }
}

// ---------------- persistent scan kernel: 512 GRU steps, weights-stationary ----------------
// 128 CTAs = 64 unit-tiles x 2 batch-tiles. Per CTA: M=128 batch, N=48 gate rows, K=1024.
// W_hh slab (hi+lo bf16) resident in smem for the entire scan.
__global__ __launch_bounds__(256, 1) void k_scan(const int *__restrict__ inputs,
                                                 const float *__restrict__ b_ih,
                                                 const float *__restrict__ b_hh) {
    extern __shared__ char smem[];
    __nv_bfloat16 *sWh = reinterpret_cast<__nv_bfloat16 *>(smem + OFF_WHI);
    __nv_bfloat16 *sWl = reinterpret_cast<__nv_bfloat16 *>(smem + OFF_WLO);
    float *sHg = reinterpret_cast<float *>(smem + OFF_REG);

    const int tid = threadIdx.x;
    const int lane = tid & 31, warp = tid >> 5;
    const int wm = warp & 3, wn = warp >> 2;      // 4 M-warps x 2 N-warps
    const int bt = blockIdx.x >> 6, ut = blockIdx.x & 63;
    const int b0 = bt * MCTA, j0 = ut * UNITS;
    const int g  = lane >> 2;
    const int c2 = (lane & 3) * 2;

    // ---- load W_hh slab into smem once (rows: gate*16 + u) ----
    for (int i = tid; i < NROWS * 128; i += 256) {
        const int row = i >> 7, c = (i & 127) * 8;
        const int wrow = (row >> 4) * HID + j0 + (row & 15);
        *reinterpret_cast<uint4 *>(&sWh[row * WST + c]) =
            *reinterpret_cast<const uint4 *>(&g_Whh_hi[(size_t)wrow * HID + c]);
        *reinterpret_cast<uint4 *>(&sWl[row * WST + c]) =
            *reinterpret_cast<const uint4 *>(&g_Whh_lo[(size_t)wrow * HID + c]);
    }

    // ---- epilogue mapping + bias preload (constant over t) ----
    const int er = tid >> 1;            // batch row 0..127
    const int u0 = (tid & 1) * 8;       // unit half
    float bsr[8], bsz[8], bin[8], bhn[8];
#pragma unroll
    for (int uu = 0; uu < 8; uu++) {
        const int j = j0 + u0 + uu;
        bsr[uu] = b_ih[j] + b_hh[j];
        bsz[uu] = b_ih[HID + j] + b_hh[HID + j];
        bin[uu] = b_ih[2 * HID + j];
        bhn[uu] = b_hh[2 * HID + j];
    }
    __syncthreads();

    for (int t = 0; t < SEQ; t++) {
        const float *hin  = (t & 1) ? g_h1 : g_h0;
        float       *hout = (t & 1) ? g_h0 : g_h1;

        // ---- prefetch E-gather rows + h_prev for epilogue ----
        const int v = inputs[(b0 + er) * SEQ + t];
        const float *Er = &g_E[(size_t)v * G3 + j0 + u0];
        float ex_r[8], ex_z[8], ex_n[8], hp[8];
        {
            float4 a0 = *reinterpret_cast<const float4 *>(Er);
            float4 a1 = *reinterpret_cast<const float4 *>(Er + 4);
            float4 z0 = *reinterpret_cast<const float4 *>(Er + HID);
            float4 z1 = *reinterpret_cast<const float4 *>(Er + HID + 4);
            float4 n0 = *reinterpret_cast<const float4 *>(Er + 2 * HID);
            float4 n1 = *reinterpret_cast<const float4 *>(Er + 2 * HID + 4);
            float4 p0 = __ldcg(reinterpret_cast<const float4 *>(&hin[(b0 + er) * HID + j0 + u0]));
            float4 p1 = __ldcg(reinterpret_cast<const float4 *>(&hin[(b0 + er) * HID + j0 + u0 + 4]));
            ex_r[0]=a0.x; ex_r[1]=a0.y; ex_r[2]=a0.z; ex_r[3]=a0.w;
            ex_r[4]=a1.x; ex_r[5]=a1.y; ex_r[6]=a1.z; ex_r[7]=a1.w;
            ex_z[0]=z0.x; ex_z[1]=z0.y; ex_z[2]=z0.z; ex_z[3]=z0.w;
            ex_z[4]=z1.x; ex_z[5]=z1.y; ex_z[6]=z1.z; ex_z[7]=z1.w;
            ex_n[0]=n0.x; ex_n[1]=n0.y; ex_n[2]=n0.z; ex_n[3]=n0.w;
            ex_n[4]=n1.x; ex_n[5]=n1.y; ex_n[6]=n1.z; ex_n[7]=n1.w;
            hp[0]=p0.x; hp[1]=p0.y; hp[2]=p0.z; hp[3]=p0.w;
            hp[4]=p1.x; hp[5]=p1.y; hp[6]=p1.z; hp[7]=p1.w;
        }

        // ---- A-staging loader (double-buffered, __ldcg: h changes within this launch) ----
        auto loadA = [&](int kt, int buf) {
            __nv_bfloat16 *Ah = reinterpret_cast<__nv_bfloat16 *>(smem + OFF_REG + buf * A_PLANE);
            __nv_bfloat16 *Al = reinterpret_cast<__nv_bfloat16 *>(smem + OFF_REG + (2 + buf) * A_PLANE);
            const int r = tid >> 1, cg = (tid & 1) * 8;
            const float *p = &hin[(b0 + r) * HID + kt * KC + cg];
            float4 v0 = __ldcg(reinterpret_cast<const float4 *>(p));
            float4 v1 = __ldcg(reinterpret_cast<const float4 *>(p + 4));
            __nv_bfloat16 h[8], l[8];
            split2(v0.x, h[0], l[0]); split2(v0.y, h[1], l[1]);
            split2(v0.z, h[2], l[2]); split2(v0.w, h[3], l[3]);
            split2(v1.x, h[4], l[4]); split2(v1.y, h[5], l[5]);
            split2(v1.z, h[6], l[6]); split2(v1.w, h[7], l[7]);
            *reinterpret_cast<uint4 *>(&Ah[r * AST + cg]) =
                make_uint4(pk(h[0], h[1]), pk(h[2], h[3]), pk(h[4], h[5]), pk(h[6], h[7]));
            *reinterpret_cast<uint4 *>(&Al[r * AST + cg]) =
                make_uint4(pk(l[0], l[1]), pk(l[2], l[3]), pk(l[4], l[5]), pk(l[6], l[7]));
        };

        float acc[2][3][4] = {};
        loadA(0, 0);
        __syncthreads();

        for (int kt = 0; kt < KT; kt++) {
            const int cur = kt & 1;
            if (kt + 1 < KT) loadA(kt + 1, cur ^ 1);
            const __nv_bfloat16 *Ah = reinterpret_cast<const __nv_bfloat16 *>(smem + OFF_REG + cur * A_PLANE);
            const __nv_bfloat16 *Al = reinterpret_cast<const __nv_bfloat16 *>(smem + OFF_REG + (2 + cur) * A_PLANE);
            const int kcol = kt * KC;

            unsigned ah[2][4], al[2][4];
#pragma unroll
            for (int mf = 0; mf < 2; mf++) {
                const int ra = wm * 32 + mf * 16 + g;
                ah[mf][0] = *reinterpret_cast<const unsigned *>(&Ah[ra * AST + c2]);
                ah[mf][1] = *reinterpret_cast<const unsigned *>(&Ah[(ra + 8) * AST + c2]);
                ah[mf][2] = *reinterpret_cast<const unsigned *>(&Ah[ra * AST + c2 + 8]);
                ah[mf][3] = *reinterpret_cast<const unsigned *>(&Ah[(ra + 8) * AST + c2 + 8]);
                al[mf][0] = *reinterpret_cast<const unsigned *>(&Al[ra * AST + c2]);
                al[mf][1] = *reinterpret_cast<const unsigned *>(&Al[(ra + 8) * AST + c2]);
                al[mf][2] = *reinterpret_cast<const unsigned *>(&Al[ra * AST + c2 + 8]);
                al[mf][3] = *reinterpret_cast<const unsigned *>(&Al[(ra + 8) * AST + c2 + 8]);
            }
#pragma unroll
            for (int nf = 0; nf < 3; nf++) {
                const int rb = wn * 24 + nf * 8 + g;
                unsigned bh[2], bl[2];
                bh[0] = *reinterpret_cast<const unsigned *>(&sWh[rb * WST + kcol + c2]);
                bh[1] = *reinterpret_cast<const unsigned *>(&sWh[rb * WST + kcol + c2 + 8]);
                bl[0] = *reinterpret_cast<const unsigned *>(&sWl[rb * WST + kcol + c2]);
                bl[1] = *reinterpret_cast<const unsigned *>(&sWl[rb * WST + kcol + c2 + 8]);
#pragma unroll
                for (int mf = 0; mf < 2; mf++) {
                    mma16816(acc[mf][nf], ah[mf], bh);
                    mma16816(acc[mf][nf], ah[mf], bl);
                    mma16816(acc[mf][nf], al[mf], bh);
                }
            }
            __syncthreads();
        }

        // ---- stage Hg to smem (overlays A buffers; safe after final sync) ----
#pragma unroll
        for (int mf = 0; mf < 2; mf++) {
#pragma unroll
            for (int nf = 0; nf < 3; nf++) {
                const int r0  = wm * 32 + mf * 16 + g;
                const int col = wn * 24 + nf * 8 + c2;
                sHg[r0 * HG_STRIDE + col]           = acc[mf][nf][0];
                sHg[r0 * HG_STRIDE + col + 1]       = acc[mf][nf][1];
                sHg[(r0 + 8) * HG_STRIDE + col]     = acc[mf][nf][2];
                sHg[(r0 + 8) * HG_STRIDE + col + 1] = acc[mf][nf][3];
            }
        }
        __syncthreads();

        // ---- fused gating + h update ----
        float outv[8];
#pragma unroll
        for (int uu = 0; uu < 8; uu++) {
            const int u = u0 + uu;
            const float hr = sHg[er * HG_STRIDE + u];
            const float hz = sHg[er * HG_STRIDE + 16 + u];
            const float hn = sHg[er * HG_STRIDE + 32 + u];
            const float rg = sigf(ex_r[uu] + hr + bsr[uu]);
            const float zg = sigf(ex_z[uu] + hz + bsz[uu]);
            const float ng = tanhf(ex_n[uu] + bin[uu] + rg * (hn + bhn[uu]));
            outv[uu] = (1.0f - zg) * ng + zg * hp[uu];
        }
        __stcg(reinterpret_cast<float4 *>(&hout[(b0 + er) * HID + j0 + u0]),
               make_float4(outv[0], outv[1], outv[2], outv[3]));
        __stcg(reinterpret_cast<float4 *>(&hout[(b0 + er) * HID + j0 + u0 + 4]),
               make_float4(outv[4], outv[5], outv[6], outv[7]));

        grid_bar((unsigned)(t + 1));
    }
}

// ---------------- kernel: zero h0 + reset barrier state ----------------
__global__ void k_zero() {
    int i = blockIdx.x * blockDim.x + threadIdx.x;
    if (i < BATCH * HID) g_h0[i] = 0.0f;
    if (i == 0) { g_count = 0; g_phase = 0; }
}

// ---------------- kernel: out = h_final @ W_dense^T + b_dense ----------------
__global__ void k_dense(const float *__restrict__ Wd, const float *__restrict__ bd,
                        float *__restrict__ out) {
    const int gw   = (blockIdx.x * (blockDim.x >> 5)) + (threadIdx.x >> 5);
    const int lane = threadIdx.x & 31;
    if (gw >= BATCH * 2) return;
    const int b = gw >> 1, o = gw & 1;
    const float *h = g_h0;   // t=511 (odd) wrote g_h0
    float s = 0.0f;
    for (int i = lane; i < HID; i += 32) s += h[b * HID + i] * Wd[o * HID + i];
#pragma unroll
    for (int off = 16; off > 0; off >>= 1) s += __shfl_xor_sync(0xFFFFFFFFu, s, off);
    if (lane == 0) out[b * 2 + o] = s + bd[o];
}

// ---------------- launch ----------------
extern "C" void kernel_launch(void *const *d_in, const int *in_sizes, int n_in,
                              void *d_out, int out_size) {
    const int   *inputs  = (const int *)d_in[0];
    const float *emb     = (const float *)d_in[1];
    const float *W_ih    = (const float *)d_in[2];
    const float *W_hh    = (const float *)d_in[3];
    const float *b_ih    = (const float *)d_in[4];
    const float *b_hh    = (const float *)d_in[5];
    const float *W_dense = (const float *)d_in[6];
    const float *b_dense = (const float *)d_in[7];
    float *out = (float *)d_out;

    cudaFuncSetAttribute(k_scan, cudaFuncAttributeMaxDynamicSharedMemorySize, SMEM_TOTAL);

    k_split<<<6144, 1024>>>(W_ih, W_hh);
    k_vocab<<<dim3(24, 250), 256>>>(emb);
    k_zero<<<256, 1024>>>();
    k_scan<<<NCTA, 256, SMEM_TOTAL>>>(inputs, b_ih, b_hh);
    k_dense<<<64, 256>>>(W_dense, b_dense, out);
}

// round 7
// speedup vs baseline: 1.2495x; 1.2495x over previous
#include <cuda_runtime.h>
#include <cuda_bf16.h>
#include <cstdint>
#include <cstddef>

#define HID   1024
#define BATCH 256
#define SEQ   512
#define VOCAB 32000
#define G3    3072   // 3*HID

// persistent-scan geometry
#define NCTA  128
#define UNITS 16          // hidden units per CTA
#define NROWS 48          // 3 gates * UNITS
#define MCTA  128         // batch rows per CTA
#define WST   1032        // smem W stride (bf16), conflict-free
#define KT    64          // K iterations of 16

// dynamic smem layout (bytes)
#define OFF_WHI 0
#define OFF_WLO (NROWS * WST * 2)            // 99072
#define OFF_HG  (2 * NROWS * WST * 2)        // 198144
#define HG_STRIDE 51
#define SMEM_TOTAL (OFF_HG + MCTA * HG_STRIDE * 4)   // 224256

// ---------------- persistent scratch ----------------
__device__ __nv_bfloat16 g_Wih_hi[G3 * HID];
__device__ __nv_bfloat16 g_Wih_lo[G3 * HID];
__device__ __nv_bfloat16 g_Whh_hi[G3 * HID];
__device__ __nv_bfloat16 g_Whh_lo[G3 * HID];
__device__ float         g_E[(size_t)VOCAB * G3];   // emb @ W_ih^T
// h state: DOUBLE-BUFFERED bf16 hi/lo planes (read plane t&1, write plane (t+1)&1).
// R6 bug: single-buffered planes raced (fast CTA's write vs slow CTA's read).
__device__ __nv_bfloat16 g_hhi[2][BATCH * HID];
__device__ __nv_bfloat16 g_hlo[2][BATCH * HID];
__device__ float         g_hfin[BATCH * HID];       // fp32 h at t=511 (for dense head)
__device__ unsigned      g_count = 0;
__device__ unsigned      g_phase = 0;

// ---------------- helpers ----------------
__device__ __forceinline__ void split2(float x, __nv_bfloat16 &hi, __nv_bfloat16 &lo) {
    hi = __float2bfloat16_rn(x);
    lo = __float2bfloat16_rn(x - __bfloat162float(hi));
}
__device__ __forceinline__ unsigned pk(__nv_bfloat16 a, __nv_bfloat16 b) {
    return (unsigned)__bfloat16_as_ushort(a) | ((unsigned)__bfloat16_as_ushort(b) << 16);
}
__device__ __forceinline__ void mma16816(float *d, const unsigned *a, const unsigned *b) {
    asm volatile(
        "mma.sync.aligned.m16n8k16.row.col.f32.bf16.bf16.f32 "
        "{%0,%1,%2,%3},{%4,%5,%6,%7},{%8,%9},{%0,%1,%2,%3};\n"
        : "+f"(d[0]), "+f"(d[1]), "+f"(d[2]), "+f"(d[3])
        : "r"(a[0]), "r"(a[1]), "r"(a[2]), "r"(a[3]), "r"(b[0]), "r"(b[1]));
}
__device__ __forceinline__ float sigf(float x) { return 1.0f / (1.0f + __expf(-x)); }

// Grid barrier, hang-proofed bounded spin.
__device__ __forceinline__ void grid_bar(unsigned target) {
    __threadfence();
    __syncthreads();
    if (threadIdx.x == 0) {
        unsigned a = atomicAdd(&g_count, 1u);
        if (a == NCTA - 1) {
            g_count = 0;
            __threadfence();
            atomicExch(&g_phase, target);
        } else {
            for (int spin = 0; spin < 200000; ++spin) {
                if (atomicAdd(&g_phase, 0u) == target) break;
                __nanosleep(64);
            }
        }
        __threadfence();
    }
    __syncthreads();
}

// ---------------- kernel: split weights into bf16 hi/lo ----------------
__global__ void k_split(const float *__restrict__ Wih, const float *__restrict__ Whh) {
    int i = blockIdx.x * blockDim.x + threadIdx.x;
    const int N = G3 * HID;
    if (i < N) {
        split2(Wih[i], g_Wih_hi[i], g_Wih_lo[i]);
    } else {
        int j = i - N;
        split2(Whh[j], g_Whh_hi[j], g_Whh_lo[j]);
    }
}

// ---------------- kernel: E = emb @ W_ih^T  (M=32000, N=3072, K=1024) ----------------
__global__ __launch_bounds__(256) void k_vocab(const float *__restrict__ emb) {
    __shared__ __nv_bfloat16 sA_hi[128 * 40];
    __shared__ __nv_bfloat16 sA_lo[128 * 40];
    __shared__ __nv_bfloat16 sB_hi[128 * 40];
    __shared__ __nv_bfloat16 sB_lo[128 * 40];

    const int tid = threadIdx.x;
    const int lane = tid & 31, warp = tid >> 5;
    const int wm = warp & 1, wn = warp >> 1;
    const int m0 = blockIdx.y * 128, n0 = blockIdx.x * 128;

    float acc[4][4][4] = {};
    const int g  = lane >> 2;
    const int c2 = (lane & 3) * 2;

    for (int kt = 0; kt < 32; ++kt) {
        const int k0 = kt * 32;
        __syncthreads();
        {
            const int r_ = tid >> 3, c4 = (tid & 7) * 4;
#pragma unroll
            for (int i = 0; i < 4; i++) {
                const int row = r_ + i * 32;
                float4 v = *reinterpret_cast<const float4 *>(
                    &emb[(size_t)(m0 + row) * HID + k0 + c4]);
                __nv_bfloat16 h0, h1, h2, h3, l0, l1, l2, l3;
                split2(v.x, h0, l0); split2(v.y, h1, l1);
                split2(v.z, h2, l2); split2(v.w, h3, l3);
                unsigned *ph = reinterpret_cast<unsigned *>(&sA_hi[row * 40 + c4]);
                ph[0] = pk(h0, h1); ph[1] = pk(h2, h3);
                unsigned *pl = reinterpret_cast<unsigned *>(&sA_lo[row * 40 + c4]);
                pl[0] = pk(l0, l1); pl[1] = pk(l2, l3);
            }
        }
        {
            const int rb = tid >> 2, q = tid & 3;
#pragma unroll
            for (int i = 0; i < 2; i++) {
                const int row = rb + i * 64;
                *reinterpret_cast<uint4 *>(&sB_hi[row * 40 + q * 8]) =
                    *reinterpret_cast<const uint4 *>(&g_Wih_hi[(size_t)(n0 + row) * HID + k0 + q * 8]);
                *reinterpret_cast<uint4 *>(&sB_lo[row * 40 + q * 8]) =
                    *reinterpret_cast<const uint4 *>(&g_Wih_lo[(size_t)(n0 + row) * HID + k0 + q * 8]);
            }
        }
        __syncthreads();

#pragma unroll
        for (int kk = 0; kk < 32; kk += 16) {
            unsigned ah[4][4], al[4][4];
#pragma unroll
            for (int mf = 0; mf < 4; mf++) {
                const int ra = wm * 64 + mf * 16 + g;
                ah[mf][0] = *reinterpret_cast<unsigned *>(&sA_hi[ra * 40 + kk + c2]);
                ah[mf][1] = *reinterpret_cast<unsigned *>(&sA_hi[(ra + 8) * 40 + kk + c2]);
                ah[mf][2] = *reinterpret_cast<unsigned *>(&sA_hi[ra * 40 + kk + c2 + 8]);
                ah[mf][3] = *reinterpret_cast<unsigned *>(&sA_hi[(ra + 8) * 40 + kk + c2 + 8]);
                al[mf][0] = *reinterpret_cast<unsigned *>(&sA_lo[ra * 40 + kk + c2]);
                al[mf][1] = *reinterpret_cast<unsigned *>(&sA_lo[(ra + 8) * 40 + kk + c2]);
                al[mf][2] = *reinterpret_cast<unsigned *>(&sA_lo[ra * 40 + kk + c2 + 8]);
                al[mf][3] = *reinterpret_cast<unsigned *>(&sA_lo[(ra + 8) * 40 + kk + c2 + 8]);
            }
#pragma unroll
            for (int nf = 0; nf < 4; nf++) {
                const int rb_ = wn * 32 + nf * 8 + g;
                unsigned bh[2], bl[2];
                bh[0] = *reinterpret_cast<unsigned *>(&sB_hi[rb_ * 40 + kk + c2]);
                bh[1] = *reinterpret_cast<unsigned *>(&sB_hi[rb_ * 40 + kk + c2 + 8]);
                bl[0] = *reinterpret_cast<unsigned *>(&sB_lo[rb_ * 40 + kk + c2]);
                bl[1] = *reinterpret_cast<unsigned *>(&sB_lo[rb_ * 40 + kk + c2 + 8]);
#pragma unroll
                for (int mf = 0; mf < 4; mf++) {
                    mma16816(acc[mf][nf], ah[mf], bh);
                    mma16816(acc[mf][nf], ah[mf], bl);
                    mma16816(acc[mf][nf], al[mf], bh);
                }
            }
        }
    }

#pragma unroll
    for (int mf = 0; mf < 4; mf++) {
#pragma unroll
        for (int nf = 0; nf < 4; nf++) {
            const int row = m0 + wm * 64 + mf * 16 + g;
            const int col = n0 + wn * 32 + nf * 8 + c2;
            *reinterpret_cast<float2 *>(&g_E[(size_t)row * G3 + col]) =
                make_float2(acc[mf][nf][0], acc[mf][nf][1]);
            *reinterpret_cast<float2 *>(&g_E[(size_t)(row + 8) * G3 + col]) =
                make_float2(acc[mf][nf][2], acc[mf][nf][3]);
        }
    }
}

// ---------------- persistent scan: barrier-free K-loop, double-buffered h ----------------
// 128 CTAs = 64 unit-tiles x 2 batch-halves. Per CTA: M=128, N=48, K=1024.
__global__ __launch_bounds__(256, 1) void k_scan(const int *__restrict__ inputs,
                                                 const float *__restrict__ b_ih,
                                                 const float *__restrict__ b_hh) {
    extern __shared__ char smem[];
    __nv_bfloat16 *sWh = reinterpret_cast<__nv_bfloat16 *>(smem + OFF_WHI);
    __nv_bfloat16 *sWl = reinterpret_cast<__nv_bfloat16 *>(smem + OFF_WLO);
    float *sHg = reinterpret_cast<float *>(smem + OFF_HG);

    const int tid  = threadIdx.x;
    const int lane = tid & 31, warp = tid >> 5;   // 8 warps
    const int bt = blockIdx.x >> 6, ut = blockIdx.x & 63;
    const int b0 = bt * MCTA, j0 = ut * UNITS;
    const int g  = lane >> 2;
    const int c2 = (lane & 3) * 2;

    // ---- load W_hh slab into smem once ----
    for (int i = tid; i < NROWS * 128; i += 256) {
        const int row = i >> 7, c = (i & 127) * 8;
        const int wrow = (row >> 4) * HID + j0 + (row & 15);
        *reinterpret_cast<uint4 *>(&sWh[row * WST + c]) =
            *reinterpret_cast<const uint4 *>(&g_Whh_hi[(size_t)wrow * HID + c]);
        *reinterpret_cast<uint4 *>(&sWl[row * WST + c]) =
            *reinterpret_cast<const uint4 *>(&g_Whh_lo[(size_t)wrow * HID + c]);
    }

    // ---- epilogue mapping + bias preload ----
    const int er = tid >> 1;            // batch row 0..127
    const int u0 = (tid & 1) * 8;       // unit half
    float bsr[8], bsz[8], bin[8], bhn[8];
#pragma unroll
    for (int uu = 0; uu < 8; uu++) {
        const int j = j0 + u0 + uu;
        bsr[uu] = b_ih[j] + b_hh[j];
        bsz[uu] = b_ih[HID + j] + b_hh[HID + j];
        bin[uu] = b_ih[2 * HID + j];
        bhn[uu] = b_hh[2 * HID + j];
    }
    const size_t hoff = (size_t)(b0 + er) * HID + j0 + u0;
    __syncthreads();

    const int ra = warp * 16 + g;                       // A fragment row
    const size_t abase0 = (size_t)(b0 + ra) * HID + c2; // + kcol per iter

    for (int t = 0; t < SEQ; t++) {
        const int rp = t & 1, wp = rp ^ 1;   // read plane / write plane
        const __nv_bfloat16 *hhiR = g_hhi[rp], *hloR = g_hlo[rp];
        __nv_bfloat16 *hhiW = g_hhi[wp], *hloW = g_hlo[wp];

        // ---- prefetch E-gather rows + h_prev for epilogue ----
        const int v = inputs[(b0 + er) * SEQ + t];
        const float *Er = &g_E[(size_t)v * G3 + j0 + u0];
        float4 exr0 = *reinterpret_cast<const float4 *>(Er);
        float4 exr1 = *reinterpret_cast<const float4 *>(Er + 4);
        float4 exz0 = *reinterpret_cast<const float4 *>(Er + HID);
        float4 exz1 = *reinterpret_cast<const float4 *>(Er + HID + 4);
        float4 exn0 = *reinterpret_cast<const float4 *>(Er + 2 * HID);
        float4 exn1 = *reinterpret_cast<const float4 *>(Er + 2 * HID + 4);
        uint4 phi = __ldcg(reinterpret_cast<const uint4 *>(&hhiR[hoff]));
        uint4 plo = __ldcg(reinterpret_cast<const uint4 *>(&hloR[hoff]));

        float acc[6][4] = {};

#pragma unroll 2
        for (int kt = 0; kt < KT; kt++) {
            const int kcol = kt * 16;
            // A fragments straight from L2 (bf16 planes), no smem, no barriers
            unsigned ah[4], al[4];
            {
                const __nv_bfloat16 *ph = hhiR + abase0 + kcol;
                const __nv_bfloat16 *pl = hloR + abase0 + kcol;
                ah[0] = __ldcg(reinterpret_cast<const unsigned *>(ph));
                ah[1] = __ldcg(reinterpret_cast<const unsigned *>(ph + 8 * HID));
                ah[2] = __ldcg(reinterpret_cast<const unsigned *>(ph + 8));
                ah[3] = __ldcg(reinterpret_cast<const unsigned *>(ph + 8 * HID + 8));
                al[0] = __ldcg(reinterpret_cast<const unsigned *>(pl));
                al[1] = __ldcg(reinterpret_cast<const unsigned *>(pl + 8 * HID));
                al[2] = __ldcg(reinterpret_cast<const unsigned *>(pl + 8));
                al[3] = __ldcg(reinterpret_cast<const unsigned *>(pl + 8 * HID + 8));
            }
            unsigned bh[6][2], bl[6][2];
#pragma unroll
            for (int nf = 0; nf < 6; nf++) {
                const int rb = nf * 8 + g;
                bh[nf][0] = *reinterpret_cast<const unsigned *>(&sWh[rb * WST + kcol + c2]);
                bh[nf][1] = *reinterpret_cast<const unsigned *>(&sWh[rb * WST + kcol + c2 + 8]);
                bl[nf][0] = *reinterpret_cast<const unsigned *>(&sWl[rb * WST + kcol + c2]);
                bl[nf][1] = *reinterpret_cast<const unsigned *>(&sWl[rb * WST + kcol + c2 + 8]);
            }
            // three passes over 6 independent accumulator chains (ILP)
#pragma unroll
            for (int nf = 0; nf < 6; nf++) mma16816(acc[nf], ah, bh[nf]);
#pragma unroll
            for (int nf = 0; nf < 6; nf++) mma16816(acc[nf], ah, bl[nf]);
#pragma unroll
            for (int nf = 0; nf < 6; nf++) mma16816(acc[nf], al, bh[nf]);
        }

        // ---- stage Hg to smem ----
#pragma unroll
        for (int nf = 0; nf < 6; nf++) {
            const int r0  = warp * 16 + g;
            const int col = nf * 8 + c2;
            sHg[r0 * HG_STRIDE + col]           = acc[nf][0];
            sHg[r0 * HG_STRIDE + col + 1]       = acc[nf][1];
            sHg[(r0 + 8) * HG_STRIDE + col]     = acc[nf][2];
            sHg[(r0 + 8) * HG_STRIDE + col + 1] = acc[nf][3];
        }
        __syncthreads();

        // ---- fused gating + h update (hp = hi + lo reconstruction) ----
        const unsigned *phw = reinterpret_cast<const unsigned *>(&phi);
        const unsigned *plw = reinterpret_cast<const unsigned *>(&plo);
        float ex_r[8] = {exr0.x, exr0.y, exr0.z, exr0.w, exr1.x, exr1.y, exr1.z, exr1.w};
        float ex_z[8] = {exz0.x, exz0.y, exz0.z, exz0.w, exz1.x, exz1.y, exz1.z, exz1.w};
        float ex_n[8] = {exn0.x, exn0.y, exn0.z, exn0.w, exn1.x, exn1.y, exn1.z, exn1.w};
        float outv[8];
#pragma unroll
        for (int uu = 0; uu < 8; uu++) {
            const int u = u0 + uu;
            const float hr = sHg[er * HG_STRIDE + u];
            const float hz = sHg[er * HG_STRIDE + 16 + u];
            const float hn = sHg[er * HG_STRIDE + 32 + u];
            const unsigned wh = phw[uu >> 1], wl = plw[uu >> 1];
            const unsigned sh = (uu & 1) ? (wh >> 16) : (wh & 0xFFFF);
            const unsigned sl = (uu & 1) ? (wl >> 16) : (wl & 0xFFFF);
            const float hp = __bfloat162float(__ushort_as_bfloat16((unsigned short)sh)) +
                             __bfloat162float(__ushort_as_bfloat16((unsigned short)sl));
            const float rg = sigf(ex_r[uu] + hr + bsr[uu]);
            const float zg = sigf(ex_z[uu] + hz + bsz[uu]);
            const float ng = tanhf(ex_n[uu] + bin[uu] + rg * (hn + bhn[uu]));
            outv[uu] = (1.0f - zg) * ng + zg * hp;
        }
        // write new h as split bf16 planes (to the WRITE plane — no aliasing with reads)
        __nv_bfloat16 oh[8], ol[8];
#pragma unroll
        for (int uu = 0; uu < 8; uu++) split2(outv[uu], oh[uu], ol[uu]);
        __stcg(reinterpret_cast<uint4 *>(&hhiW[hoff]),
               make_uint4(pk(oh[0], oh[1]), pk(oh[2], oh[3]), pk(oh[4], oh[5]), pk(oh[6], oh[7])));
        __stcg(reinterpret_cast<uint4 *>(&hloW[hoff]),
               make_uint4(pk(ol[0], ol[1]), pk(ol[2], ol[3]), pk(ol[4], ol[5]), pk(ol[6], ol[7])));
        if (t == SEQ - 1) {
            *reinterpret_cast<float4 *>(&g_hfin[hoff]) =
                make_float4(outv[0], outv[1], outv[2], outv[3]);
            *reinterpret_cast<float4 *>(&g_hfin[hoff + 4]) =
                make_float4(outv[4], outv[5], outv[6], outv[7]);
        }

        grid_bar((unsigned)(t + 1));
    }
}

// ---------------- kernel: zero h planes + reset barrier state ----------------
__global__ void k_zero() {
    int i = blockIdx.x * blockDim.x + threadIdx.x;
    if (i < BATCH * HID) {
        g_hhi[0][i] = __float2bfloat16(0.0f);
        g_hlo[0][i] = __float2bfloat16(0.0f);
    }
    if (i == 0) { g_count = 0; g_phase = 0; }
}

// ---------------- kernel: out = h_final @ W_dense^T + b_dense ----------------
__global__ void k_dense(const float *__restrict__ Wd, const float *__restrict__ bd,
                        float *__restrict__ out) {
    const int gw   = (blockIdx.x * (blockDim.x >> 5)) + (threadIdx.x >> 5);
    const int lane = threadIdx.x & 31;
    if (gw >= BATCH * 2) return;
    const int b = gw >> 1, o = gw & 1;
    float s = 0.0f;
    for (int i = lane; i < HID; i += 32) s += g_hfin[b * HID + i] * Wd[o * HID + i];
#pragma unroll
    for (int off = 16; off > 0; off >>= 1) s += __shfl_xor_sync(0xFFFFFFFFu, s, off);
    if (lane == 0) out[b * 2 + o] = s + bd[o];
}

// ---------------- launch ----------------
extern "C" void kernel_launch(void *const *d_in, const int *in_sizes, int n_in,
                              void *d_out, int out_size) {
    const int   *inputs  = (const int *)d_in[0];
    const float *emb     = (const float *)d_in[1];
    const float *W_ih    = (const float *)d_in[2];
    const float *W_hh    = (const float *)d_in[3];
    const float *b_ih    = (const float *)d_in[4];
    const float *b_hh    = (const float *)d_in[5];
    const float *W_dense = (const float *)d_in[6];
    const float *b_dense = (const float *)d_in[7];
    float *out = (float *)d_out;

    cudaFuncSetAttribute(k_scan, cudaFuncAttributeMaxDynamicSharedMemorySize, SMEM_TOTAL);

    k_split<<<6144, 1024>>>(W_ih, W_hh);
    k_vocab<<<dim3(24, 250), 256>>>(emb);
    k_zero<<<256, 1024>>>();
    k_scan<<<NCTA, 256, SMEM_TOTAL>>>(inputs, b_ih, b_hh);
    k_dense<<<64, 256>>>(W_dense, b_dense, out);
}

// round 9
// speedup vs baseline: 2.4110x; 1.9295x over previous
#include <cuda_runtime.h>
#include <cuda_bf16.h>
#include <cstdint>
#include <cstddef>

#define HID   1024
#define BATCH 256
#define SEQ   512
#define VOCAB 32000
#define G3    3072   // 3*HID

// persistent-scan geometry
#define NCTA  128
#define UNITS 16          // hidden units per CTA
#define NROWS 48          // 3 gates * UNITS
#define MCTA  128         // batch rows per CTA
#define KT    64          // K iterations of 16

// dynamic smem layout (bytes): W fragment-major hi/lo + Hg staging
#define OFF_WFH 0
#define WF_WORDS (6 * 64 * 32 * 2)            // 24576 uint32 per plane
#define OFF_WFL (WF_WORDS * 4)                // 98304
#define OFF_HG  (2 * WF_WORDS * 4)            // 196608
#define HG_STRIDE 51
#define SMEM_TOTAL (OFF_HG + MCTA * HG_STRIDE * 4)   // 222720

// ---------------- persistent scratch ----------------
__device__ __nv_bfloat16 g_Wih_hi[G3 * HID];
__device__ __nv_bfloat16 g_Wih_lo[G3 * HID];
__device__ __nv_bfloat16 g_Whh_hi[G3 * HID];
__device__ __nv_bfloat16 g_Whh_lo[G3 * HID];
__device__ float         g_E[(size_t)VOCAB * G3];   // emb @ W_ih^T
// h state, double-buffered, FRAGMENT-MAJOR bf16 planes:
// index ((m*64 + kt)*32 + lane)*4 + word, word order = {(g,c2),(g+8,c2),(g,c2+8),(g+8,c2+8)}
__device__ unsigned g_hfh[2][16 * 64 * 32 * 4];
__device__ unsigned g_hfl[2][16 * 64 * 32 * 4];
// h state, double-buffered linear fp32 (epilogue h_prev read + dense head)
__device__ float    g_hlin[2][BATCH * HID];
__device__ unsigned g_count = 0;
__device__ unsigned g_phase = 0;

// ---------------- helpers ----------------
__device__ __forceinline__ void split2(float x, __nv_bfloat16 &hi, __nv_bfloat16 &lo) {
    hi = __float2bfloat16_rn(x);
    lo = __float2bfloat16_rn(x - __bfloat162float(hi));
}
__device__ __forceinline__ unsigned pk(__nv_bfloat16 a, __nv_bfloat16 b) {
    return (unsigned)__bfloat16_as_ushort(a) | ((unsigned)__bfloat16_as_ushort(b) << 16);
}
__device__ __forceinline__ void mma16816(float *d, const unsigned *a, const unsigned *b) {
    asm volatile(
        "mma.sync.aligned.m16n8k16.row.col.f32.bf16.bf16.f32 "
        "{%0,%1,%2,%3},{%4,%5,%6,%7},{%8,%9},{%0,%1,%2,%3};\n"
        : "+f"(d[0]), "+f"(d[1]), "+f"(d[2]), "+f"(d[3])
        : "r"(a[0]), "r"(a[1]), "r"(a[2]), "r"(a[3]), "r"(b[0]), "r"(b[1]));
}
__device__ __forceinline__ float sigf(float x) { return 1.0f / (1.0f + __expf(-x)); }

// Grid barrier, hang-proofed bounded spin.
__device__ __forceinline__ void grid_bar(unsigned target) {
    __threadfence();
    __syncthreads();
    if (threadIdx.x == 0) {
        unsigned a = atomicAdd(&g_count, 1u);
        if (a == NCTA - 1) {
            g_count = 0;
            __threadfence();
            atomicExch(&g_phase, target);
        } else {
            for (int spin = 0; spin < 200000; ++spin) {
                if (atomicAdd(&g_phase, 0u) == target) break;
                __nanosleep(64);
            }
        }
        __threadfence();
    }
    __syncthreads();
}

// ---------------- kernel: split weights into bf16 hi/lo ----------------
__global__ void k_split(const float *__restrict__ Wih, const float *__restrict__ Whh) {
    int i = blockIdx.x * blockDim.x + threadIdx.x;
    const int N = G3 * HID;
    if (i < N) {
        split2(Wih[i], g_Wih_hi[i], g_Wih_lo[i]);
    } else {
        int j = i - N;
        split2(Whh[j], g_Whh_hi[j], g_Whh_lo[j]);
    }
}

// ---------------- kernel: E = emb @ W_ih^T  (M=32000, N=3072, K=1024) ----------------
__global__ __launch_bounds__(256) void k_vocab(const float *__restrict__ emb) {
    __shared__ __nv_bfloat16 sA_hi[128 * 40];
    __shared__ __nv_bfloat16 sA_lo[128 * 40];
    __shared__ __nv_bfloat16 sB_hi[128 * 40];
    __shared__ __nv_bfloat16 sB_lo[128 * 40];

    const int tid = threadIdx.x;
    const int lane = tid & 31, warp = tid >> 5;
    const int wm = warp & 1, wn = warp >> 1;
    const int m0 = blockIdx.y * 128, n0 = blockIdx.x * 128;

    float acc[4][4][4] = {};
    const int g  = lane >> 2;
    const int c2 = (lane & 3) * 2;

    for (int kt = 0; kt < 32; ++kt) {
        const int k0 = kt * 32;
        __syncthreads();
        {
            const int r_ = tid >> 3, c4 = (tid & 7) * 4;
#pragma unroll
            for (int i = 0; i < 4; i++) {
                const int row = r_ + i * 32;
                float4 v = *reinterpret_cast<const float4 *>(
                    &emb[(size_t)(m0 + row) * HID + k0 + c4]);
                __nv_bfloat16 h0, h1, h2, h3, l0, l1, l2, l3;
                split2(v.x, h0, l0); split2(v.y, h1, l1);
                split2(v.z, h2, l2); split2(v.w, h3, l3);
                unsigned *ph = reinterpret_cast<unsigned *>(&sA_hi[row * 40 + c4]);
                ph[0] = pk(h0, h1); ph[1] = pk(h2, h3);
                unsigned *pl = reinterpret_cast<unsigned *>(&sA_lo[row * 40 + c4]);
                pl[0] = pk(l0, l1); pl[1] = pk(l2, l3);
            }
        }
        {
            const int rb = tid >> 2, q = tid & 3;
#pragma unroll
            for (int i = 0; i < 2; i++) {
                const int row = rb + i * 64;
                *reinterpret_cast<uint4 *>(&sB_hi[row * 40 + q * 8]) =
                    *reinterpret_cast<const uint4 *>(&g_Wih_hi[(size_t)(n0 + row) * HID + k0 + q * 8]);
                *reinterpret_cast<uint4 *>(&sB_lo[row * 40 + q * 8]) =
                    *reinterpret_cast<const uint4 *>(&g_Wih_lo[(size_t)(n0 + row) * HID + k0 + q * 8]);
            }
        }
        __syncthreads();

#pragma unroll
        for (int kk = 0; kk < 32; kk += 16) {
            unsigned ah[4][4], al[4][4];
#pragma unroll
            for (int mf = 0; mf < 4; mf++) {
                const int ra = wm * 64 + mf * 16 + g;
                ah[mf][0] = *reinterpret_cast<unsigned *>(&sA_hi[ra * 40 + kk + c2]);
                ah[mf][1] = *reinterpret_cast<unsigned *>(&sA_hi[(ra + 8) * 40 + kk + c2]);
                ah[mf][2] = *reinterpret_cast<unsigned *>(&sA_hi[ra * 40 + kk + c2 + 8]);
                ah[mf][3] = *reinterpret_cast<unsigned *>(&sA_hi[(ra + 8) * 40 + kk + c2 + 8]);
                al[mf][0] = *reinterpret_cast<unsigned *>(&sA_lo[ra * 40 + kk + c2]);
                al[mf][1] = *reinterpret_cast<unsigned *>(&sA_lo[(ra + 8) * 40 + kk + c2]);
                al[mf][2] = *reinterpret_cast<unsigned *>(&sA_lo[ra * 40 + kk + c2 + 8]);
                al[mf][3] = *reinterpret_cast<unsigned *>(&sA_lo[(ra + 8) * 40 + kk + c2 + 8]);
            }
#pragma unroll
            for (int nf = 0; nf < 4; nf++) {
                const int rb_ = wn * 32 + nf * 8 + g;
                unsigned bh[2], bl[2];
                bh[0] = *reinterpret_cast<unsigned *>(&sB_hi[rb_ * 40 + kk + c2]);
                bh[1] = *reinterpret_cast<unsigned *>(&sB_hi[rb_ * 40 + kk + c2 + 8]);
                bl[0] = *reinterpret_cast<unsigned *>(&sB_lo[rb_ * 40 + kk + c2]);
                bl[1] = *reinterpret_cast<unsigned *>(&sB_lo[rb_ * 40 + kk + c2 + 8]);
#pragma unroll
                for (int mf = 0; mf < 4; mf++) {
                    mma16816(acc[mf][nf], ah[mf], bh);
                    mma16816(acc[mf][nf], ah[mf], bl);
                    mma16816(acc[mf][nf], al[mf], bh);
                }
            }
        }
    }

#pragma unroll
    for (int mf = 0; mf < 4; mf++) {
#pragma unroll
        for (int nf = 0; nf < 4; nf++) {
            const int row = m0 + wm * 64 + mf * 16 + g;
            const int col = n0 + wn * 32 + nf * 8 + c2;
            *reinterpret_cast<float2 *>(&g_E[(size_t)row * G3 + col]) =
                make_float2(acc[mf][nf][0], acc[mf][nf][1]);
            *reinterpret_cast<float2 *>(&g_E[(size_t)(row + 8) * G3 + col]) =
                make_float2(acc[mf][nf][2], acc[mf][nf][3]);
        }
    }
}

// ---------------- persistent scan: fragment-major A/B, pipelined K-loop ----------------
__global__ __launch_bounds__(256, 1) void k_scan(const int *__restrict__ inputs,
                                                 const float *__restrict__ b_ih,
                                                 const float *__restrict__ b_hh) {
    extern __shared__ char smem[];
    unsigned *sWfH = reinterpret_cast<unsigned *>(smem + OFF_WFH);
    unsigned *sWfL = reinterpret_cast<unsigned *>(smem + OFF_WFL);
    float *sHg = reinterpret_cast<float *>(smem + OFF_HG);

    const int tid  = threadIdx.x;
    const int lane = tid & 31, warp = tid >> 5;   // 8 warps
    const int bt = blockIdx.x >> 6, ut = blockIdx.x & 63;
    const int b0 = bt * MCTA, j0 = ut * UNITS;
    const int g  = lane >> 2;
    const int c2 = (lane & 3) * 2;

    // ---- build fragment-major W_hh slab in smem (once) ----
    // sWf[((nf*64+kt)*32+lane)*2 + w]: w0 = W[row nf*8+g_][kt*16+c2(,+1)], w1 = +8 cols
    for (int i = tid; i < 6 * 64 * 32; i += 256) {
        const int nf = i >> 11, kt = (i >> 5) & 63, l = i & 31;
        const int g_ = l >> 2, cc = (l & 3) * 2;
        const int sr = nf * 8 + g_;
        const int wrow = (sr >> 4) * HID + j0 + (sr & 15);
        const size_t base = (size_t)wrow * HID + kt * 16 + cc;
        sWfH[(size_t)i * 2 + 0] = *reinterpret_cast<const unsigned *>(&g_Whh_hi[base]);
        sWfH[(size_t)i * 2 + 1] = *reinterpret_cast<const unsigned *>(&g_Whh_hi[base + 8]);
        sWfL[(size_t)i * 2 + 0] = *reinterpret_cast<const unsigned *>(&g_Whh_lo[base]);
        sWfL[(size_t)i * 2 + 1] = *reinterpret_cast<const unsigned *>(&g_Whh_lo[base + 8]);
    }

    // ---- epilogue mapping + bias preload ----
    const int er = tid >> 1;            // batch row 0..127
    const int u0 = (tid & 1) * 8;       // unit half
    float bsr[8], bsz[8], bin[8], bhn[8];
#pragma unroll
    for (int uu = 0; uu < 8; uu++) {
        const int j = j0 + u0 + uu;
        bsr[uu] = b_ih[j] + b_hh[j];
        bsz[uu] = b_ih[HID + j] + b_hh[HID + j];
        bin[uu] = b_ih[2 * HID + j];
        bhn[uu] = b_hh[2 * HID + j];
    }
    const size_t hoff = (size_t)(b0 + er) * HID + j0 + u0;   // linear fp32 h offset
    // fragment-store base for the epilogue (word index is thread-constant)
    const int m_w   = bt * 8 + (er >> 4);
    const int rr    = er & 15;
    const int wIdx  = ((rr >= 8) ? 1 : 0) + ((u0 >> 3) << 1);
    const size_t fragW = ((size_t)(m_w * 64 + ut) * 32 + (rr & 7) * 4) * 4 + wIdx;
    __syncthreads();

    const int m = bt * 8 + warp;                              // this warp's M-fragment
    const size_t aidx = (size_t)m * 64 * 32 + lane;           // uint4 index, + kt*32

    for (int t = 0; t < SEQ; t++) {
        const int rp = t & 1, wp = rp ^ 1;
        const uint4 *AbH = reinterpret_cast<const uint4 *>(g_hfh[rp]) + aidx;
        const uint4 *AbL = reinterpret_cast<const uint4 *>(g_hfl[rp]) + aidx;

        // ---- prefetch E-gather rows + h_prev for epilogue ----
        const int v = inputs[(b0 + er) * SEQ + t];
        const float *Er = &g_E[(size_t)v * G3 + j0 + u0];
        float4 exr0 = *reinterpret_cast<const float4 *>(Er);
        float4 exr1 = *reinterpret_cast<const float4 *>(Er + 4);
        float4 exz0 = *reinterpret_cast<const float4 *>(Er + HID);
        float4 exz1 = *reinterpret_cast<const float4 *>(Er + HID + 4);
        float4 exn0 = *reinterpret_cast<const float4 *>(Er + 2 * HID);
        float4 exn1 = *reinterpret_cast<const float4 *>(Er + 2 * HID + 4);
        float4 hp0 = __ldcg(reinterpret_cast<const float4 *>(&g_hlin[rp][hoff]));
        float4 hp1 = __ldcg(reinterpret_cast<const float4 *>(&g_hlin[rp][hoff + 4]));

        float acc[6][4] = {};

        // ---- 4-slot, distance-3 pipelined K-loop (no barriers) ----
        uint4 pAh[4], pAl[4];
        pAh[0] = __ldcg(AbH + 0 * 32); pAl[0] = __ldcg(AbL + 0 * 32);
        pAh[1] = __ldcg(AbH + 1 * 32); pAl[1] = __ldcg(AbL + 1 * 32);
        pAh[2] = __ldcg(AbH + 2 * 32); pAl[2] = __ldcg(AbL + 2 * 32);

#pragma unroll 4
        for (int kt = 0; kt < KT; kt++) {
            const int slot = kt & 3;
            if (kt + 3 < KT) {
                pAh[(kt + 3) & 3] = __ldcg(AbH + (kt + 3) * 32);
                pAl[(kt + 3) & 3] = __ldcg(AbL + (kt + 3) * 32);
            }
            // B fragments: one LDS.64 per chain per plane
            uint2 bhv[6], blv[6];
            {
                const uint2 *Bh = reinterpret_cast<const uint2 *>(sWfH) + (size_t)kt * 32 + lane;
                const uint2 *Bl = reinterpret_cast<const uint2 *>(sWfL) + (size_t)kt * 32 + lane;
#pragma unroll
                for (int nf = 0; nf < 6; nf++) {
                    bhv[nf] = Bh[(size_t)nf * 2048];
                    blv[nf] = Bl[(size_t)nf * 2048];
                }
            }
            unsigned ah[4] = {pAh[slot].x, pAh[slot].y, pAh[slot].z, pAh[slot].w};
            unsigned al[4] = {pAl[slot].x, pAl[slot].y, pAl[slot].z, pAl[slot].w};
#pragma unroll
            for (int nf = 0; nf < 6; nf++) mma16816(acc[nf], ah, reinterpret_cast<unsigned *>(&bhv[nf]));
#pragma unroll
            for (int nf = 0; nf < 6; nf++) mma16816(acc[nf], ah, reinterpret_cast<unsigned *>(&blv[nf]));
#pragma unroll
            for (int nf = 0; nf < 6; nf++) mma16816(acc[nf], al, reinterpret_cast<unsigned *>(&bhv[nf]));
        }

        // ---- stage Hg to smem ----
#pragma unroll
        for (int nf = 0; nf < 6; nf++) {
            const int r0  = warp * 16 + g;
            const int col = nf * 8 + c2;
            sHg[r0 * HG_STRIDE + col]           = acc[nf][0];
            sHg[r0 * HG_STRIDE + col + 1]       = acc[nf][1];
            sHg[(r0 + 8) * HG_STRIDE + col]     = acc[nf][2];
            sHg[(r0 + 8) * HG_STRIDE + col + 1] = acc[nf][3];
        }
        __syncthreads();

        // ---- fused gating + h update ----
        float ex_r[8] = {exr0.x, exr0.y, exr0.z, exr0.w, exr1.x, exr1.y, exr1.z, exr1.w};
        float ex_z[8] = {exz0.x, exz0.y, exz0.z, exz0.w, exz1.x, exz1.y, exz1.z, exz1.w};
        float ex_n[8] = {exn0.x, exn0.y, exn0.z, exn0.w, exn1.x, exn1.y, exn1.z, exn1.w};
        float hp[8]   = {hp0.x, hp0.y, hp0.z, hp0.w, hp1.x, hp1.y, hp1.z, hp1.w};
        float outv[8];
#pragma unroll
        for (int uu = 0; uu < 8; uu++) {
            const int u = u0 + uu;
            const float hr = sHg[er * HG_STRIDE + u];
            const float hz = sHg[er * HG_STRIDE + 16 + u];
            const float hn = sHg[er * HG_STRIDE + 32 + u];
            const float rg = sigf(ex_r[uu] + hr + bsr[uu]);
            const float zg = sigf(ex_z[uu] + hz + bsz[uu]);
            const float ng = tanhf(ex_n[uu] + bin[uu] + rg * (hn + bhn[uu]));
            outv[uu] = (1.0f - zg) * ng + zg * hp[uu];
        }
        // write new h: linear fp32 plane + fragment-major bf16 planes (write plane wp)
        __stcg(reinterpret_cast<float4 *>(&g_hlin[wp][hoff]),
               make_float4(outv[0], outv[1], outv[2], outv[3]));
        __stcg(reinterpret_cast<float4 *>(&g_hlin[wp][hoff + 4]),
               make_float4(outv[4], outv[5], outv[6], outv[7]));
        {
            unsigned *fH = g_hfh[wp] + fragW;
            unsigned *fL = g_hfl[wp] + fragW;
#pragma unroll
            for (int q = 0; q < 4; q++) {
                __nv_bfloat16 h0, h1, l0, l1;
                split2(outv[2 * q], h0, l0);
                split2(outv[2 * q + 1], h1, l1);
                __stcg(fH + (size_t)q * 4, pk(h0, h1));
                __stcg(fL + (size_t)q * 4, pk(l0, l1));
            }
        }

        grid_bar((unsigned)(t + 1));
    }
}

// ---------------- kernel: zero h planes + reset barrier state ----------------
__global__ void k_zero() {
    int i = blockIdx.x * blockDim.x + threadIdx.x;
    if (i < 16 * 64 * 32 * 4) {
        g_hfh[0][i] = 0u;
        g_hfl[0][i] = 0u;
    }
    if (i < BATCH * HID) g_hlin[0][i] = 0.0f;
    if (i == 0) { g_count = 0; g_phase = 0; }
}

// ---------------- kernel: out = h_final @ W_dense^T + b_dense ----------------
__global__ void k_dense(const float *__restrict__ Wd, const float *__restrict__ bd,
                        float *__restrict__ out) {
    const int gw   = (blockIdx.x * (blockDim.x >> 5)) + (threadIdx.x >> 5);
    const int lane = threadIdx.x & 31;
    if (gw >= BATCH * 2) return;
    const int b = gw >> 1, o = gw & 1;
    const float *h = g_hlin[0];   // t=511 (rp=1) wrote plane 0
    float s = 0.0f;
    for (int i = lane; i < HID; i += 32) s += h[b * HID + i] * Wd[o * HID + i];
#pragma unroll
    for (int off = 16; off > 0; off >>= 1) s += __shfl_xor_sync(0xFFFFFFFFu, s, off);
    if (lane == 0) out[b * 2 + o] = s + bd[o];
}

// ---------------- launch ----------------
extern "C" void kernel_launch(void *const *d_in, const int *in_sizes, int n_in,
                              void *d_out, int out_size) {
    const int   *inputs  = (const int *)d_in[0];
    const float *emb     = (const float *)d_in[1];
    const float *W_ih    = (const float *)d_in[2];
    const float *W_hh    = (const float *)d_in[3];
    const float *b_ih    = (const float *)d_in[4];
    const float *b_hh    = (const float *)d_in[5];
    const float *W_dense = (const float *)d_in[6];
    const float *b_dense = (const float *)d_in[7];
    float *out = (float *)d_out;

    cudaFuncSetAttribute(k_scan, cudaFuncAttributeMaxDynamicSharedMemorySize, SMEM_TOTAL);

    k_split<<<6144, 1024>>>(W_ih, W_hh);
    k_vocab<<<dim3(24, 250), 256>>>(emb);
    k_zero<<<256, 1024>>>();
    k_scan<<<NCTA, 256, SMEM_TOTAL>>>(inputs, b_ih, b_hh);
    k_dense<<<64, 256>>>(W_dense, b_dense, out);
}

// round 13
// speedup vs baseline: 2.4782x; 1.0279x over previous
#include <cuda_runtime.h>
#include <cuda_bf16.h>
#include <cstdint>
#include <cstddef>

#define HID   1024
#define BATCH 256
#define SEQ   512
#define VOCAB 32000
#define G3    3072   // 3*HID

// persistent-scan geometry
#define NCTA  128
#define UNITS 16          // hidden units per CTA
#define NROWS 48          // 3 gates * UNITS
#define MCTA  128         // batch rows per CTA
#define KT    64          // K iterations of 16

// dynamic smem layout (bytes): W fragment-major hi/lo + Hg staging / K-exchange
#define OFF_WFH 0
#define WF_WORDS (6 * 64 * 32 * 2)            // 24576 uint32 per plane
#define OFF_WFL (WF_WORDS * 4)                // 98304
#define OFF_HG  (2 * WF_WORDS * 4)            // 196608
#define HG_STRIDE 51
#define XC_STRIDE 49
#define SMEM_TOTAL (OFF_HG + MCTA * HG_STRIDE * 4)   // 222720

// ---------------- persistent scratch ----------------
__device__ __nv_bfloat16 g_Wih_hi[G3 * HID];
__device__ __nv_bfloat16 g_Wih_lo[G3 * HID];
__device__ __nv_bfloat16 g_Whh_hi[G3 * HID];
__device__ __nv_bfloat16 g_Whh_lo[G3 * HID];
__device__ float         g_E[(size_t)VOCAB * G3];   // emb @ W_ih^T
// h state, double-buffered, FRAGMENT-MAJOR bf16 planes:
// index ((m*64 + kt)*32 + lane)*4 + word, word order = {(g,c2),(g+8,c2),(g,c2+8),(g+8,c2+8)}
__device__ unsigned g_hfh[2][16 * 64 * 32 * 4];
__device__ unsigned g_hfl[2][16 * 64 * 32 * 4];
// h state, double-buffered linear fp32 (epilogue h_prev read + dense head)
__device__ float    g_hlin[2][BATCH * HID];
__device__ unsigned g_count = 0;
__device__ unsigned g_phase = 0;

// ---------------- helpers ----------------
__device__ __forceinline__ void split2(float x, __nv_bfloat16 &hi, __nv_bfloat16 &lo) {
    hi = __float2bfloat16_rn(x);
    lo = __float2bfloat16_rn(x - __bfloat162float(hi));
}
__device__ __forceinline__ unsigned pk(__nv_bfloat16 a, __nv_bfloat16 b) {
    return (unsigned)__bfloat16_as_ushort(a) | ((unsigned)__bfloat16_as_ushort(b) << 16);
}
__device__ __forceinline__ void mma16816(float *d, const unsigned *a, const unsigned *b) {
    asm volatile(
        "mma.sync.aligned.m16n8k16.row.col.f32.bf16.bf16.f32 "
        "{%0,%1,%2,%3},{%4,%5,%6,%7},{%8,%9},{%0,%1,%2,%3};\n"
        : "+f"(d[0]), "+f"(d[1]), "+f"(d[2]), "+f"(d[3])
        : "r"(a[0]), "r"(a[1]), "r"(a[2]), "r"(a[3]), "r"(b[0]), "r"(b[1]));
}
__device__ __forceinline__ float sigf(float x) { return 1.0f / (1.0f + __expf(-x)); }

// Grid barrier, hang-proofed bounded spin.
__device__ __forceinline__ void grid_bar(unsigned target) {
    __threadfence();
    __syncthreads();
    if (threadIdx.x == 0) {
        unsigned a = atomicAdd(&g_count, 1u);
        if (a == NCTA - 1) {
            g_count = 0;
            __threadfence();
            atomicExch(&g_phase, target);
        } else {
            for (int spin = 0; spin < 200000; ++spin) {
                if (atomicAdd(&g_phase, 0u) == target) break;
                __nanosleep(64);
            }
        }
        __threadfence();
    }
    __syncthreads();
}

// ---------------- kernel: split weights into bf16 hi/lo ----------------
__global__ void k_split(const float *__restrict__ Wih, const float *__restrict__ Whh) {
    int i = blockIdx.x * blockDim.x + threadIdx.x;
    const int N = G3 * HID;
    if (i < N) {
        split2(Wih[i], g_Wih_hi[i], g_Wih_lo[i]);
    } else {
        int j = i - N;
        split2(Whh[j], g_Whh_hi[j], g_Whh_lo[j]);
    }
}

// ---------------- kernel: E = emb @ W_ih^T  (M=32000, N=3072, K=1024) ----------------
__global__ __launch_bounds__(256) void k_vocab(const float *__restrict__ emb) {
    __shared__ __nv_bfloat16 sA_hi[128 * 40];
    __shared__ __nv_bfloat16 sA_lo[128 * 40];
    __shared__ __nv_bfloat16 sB_hi[128 * 40];
    __shared__ __nv_bfloat16 sB_lo[128 * 40];

    const int tid = threadIdx.x;
    const int lane = tid & 31, warp = tid >> 5;
    const int wm = warp & 1, wn = warp >> 1;
    const int m0 = blockIdx.y * 128, n0 = blockIdx.x * 128;

    float acc[4][4][4] = {};
    const int g  = lane >> 2;
    const int c2 = (lane & 3) * 2;

    for (int kt = 0; kt < 32; ++kt) {
        const int k0 = kt * 32;
        __syncthreads();
        {
            const int r_ = tid >> 3, c4 = (tid & 7) * 4;
#pragma unroll
            for (int i = 0; i < 4; i++) {
                const int row = r_ + i * 32;
                float4 v = *reinterpret_cast<const float4 *>(
                    &emb[(size_t)(m0 + row) * HID + k0 + c4]);
                __nv_bfloat16 h0, h1, h2, h3, l0, l1, l2, l3;
                split2(v.x, h0, l0); split2(v.y, h1, l1);
                split2(v.z, h2, l2); split2(v.w, h3, l3);
                unsigned *ph = reinterpret_cast<unsigned *>(&sA_hi[row * 40 + c4]);
                ph[0] = pk(h0, h1); ph[1] = pk(h2, h3);
                unsigned *pl = reinterpret_cast<unsigned *>(&sA_lo[row * 40 + c4]);
                pl[0] = pk(l0, l1); pl[1] = pk(l2, l3);
            }
        }
        {
            const int rb = tid >> 2, q = tid & 3;
#pragma unroll
            for (int i = 0; i < 2; i++) {
                const int row = rb + i * 64;
                *reinterpret_cast<uint4 *>(&sB_hi[row * 40 + q * 8]) =
                    *reinterpret_cast<const uint4 *>(&g_Wih_hi[(size_t)(n0 + row) * HID + k0 + q * 8]);
                *reinterpret_cast<uint4 *>(&sB_lo[row * 40 + q * 8]) =
                    *reinterpret_cast<const uint4 *>(&g_Wih_lo[(size_t)(n0 + row) * HID + k0 + q * 8]);
            }
        }
        __syncthreads();

#pragma unroll
        for (int kk = 0; kk < 32; kk += 16) {
            unsigned ah[4][4], al[4][4];
#pragma unroll
            for (int mf = 0; mf < 4; mf++) {
                const int ra = wm * 64 + mf * 16 + g;
                ah[mf][0] = *reinterpret_cast<unsigned *>(&sA_hi[ra * 40 + kk + c2]);
                ah[mf][1] = *reinterpret_cast<unsigned *>(&sA_hi[(ra + 8) * 40 + kk + c2]);
                ah[mf][2] = *reinterpret_cast<unsigned *>(&sA_hi[ra * 40 + kk + c2 + 8]);
                ah[mf][3] = *reinterpret_cast<unsigned *>(&sA_hi[(ra + 8) * 40 + kk + c2 + 8]);
                al[mf][0] = *reinterpret_cast<unsigned *>(&sA_lo[ra * 40 + kk + c2]);
                al[mf][1] = *reinterpret_cast<unsigned *>(&sA_lo[(ra + 8) * 40 + kk + c2]);
                al[mf][2] = *reinterpret_cast<unsigned *>(&sA_lo[ra * 40 + kk + c2 + 8]);
                al[mf][3] = *reinterpret_cast<unsigned *>(&sA_lo[(ra + 8) * 40 + kk + c2 + 8]);
            }
#pragma unroll
            for (int nf = 0; nf < 4; nf++) {
                const int rb_ = wn * 32 + nf * 8 + g;
                unsigned bh[2], bl[2];
                bh[0] = *reinterpret_cast<unsigned *>(&sB_hi[rb_ * 40 + kk + c2]);
                bh[1] = *reinterpret_cast<unsigned *>(&sB_hi[rb_ * 40 + kk + c2 + 8]);
                bl[0] = *reinterpret_cast<unsigned *>(&sB_lo[rb_ * 40 + kk + c2]);
                bl[1] = *reinterpret_cast<unsigned *>(&sB_lo[rb_ * 40 + kk + c2 + 8]);
#pragma unroll
                for (int mf = 0; mf < 4; mf++) {
                    mma16816(acc[mf][nf], ah[mf], bh);
                    mma16816(acc[mf][nf], ah[mf], bl);
                    mma16816(acc[mf][nf], al[mf], bh);
                }
            }
        }
    }

#pragma unroll
    for (int mf = 0; mf < 4; mf++) {
#pragma unroll
        for (int nf = 0; nf < 4; nf++) {
            const int row = m0 + wm * 64 + mf * 16 + g;
            const int col = n0 + wn * 32 + nf * 8 + c2;
            *reinterpret_cast<float2 *>(&g_E[(size_t)row * G3 + col]) =
                make_float2(acc[mf][nf][0], acc[mf][nf][1]);
            *reinterpret_cast<float2 *>(&g_E[(size_t)(row + 8) * G3 + col]) =
                make_float2(acc[mf][nf][2], acc[mf][nf][3]);
        }
    }
}

// ---------------- persistent scan: K-split warps (2 K-halves x 4 M-quarters) ----------------
__global__ __launch_bounds__(256, 1) void k_scan(const int *__restrict__ inputs,
                                                 const float *__restrict__ b_ih,
                                                 const float *__restrict__ b_hh) {
    extern __shared__ char smem[];
    unsigned *sWfH = reinterpret_cast<unsigned *>(smem + OFF_WFH);
    unsigned *sWfL = reinterpret_cast<unsigned *>(smem + OFF_WFL);
    float *sHg = reinterpret_cast<float *>(smem + OFF_HG);

    const int tid  = threadIdx.x;
    const int lane = tid & 31, warp = tid >> 5;   // 8 warps
    const int kh = warp >> 2;                     // K half (0/1)
    const int mq = warp & 3;                      // M quarter
    const int bt = blockIdx.x >> 6, ut = blockIdx.x & 63;
    const int b0 = bt * MCTA, j0 = ut * UNITS;
    const int g  = lane >> 2;
    const int c2 = (lane & 3) * 2;

    // ---- build fragment-major W_hh slab in smem (once) ----
    for (int i = tid; i < 6 * 64 * 32; i += 256) {
        const int nf = i >> 11, kt = (i >> 5) & 63, l = i & 31;
        const int g_ = l >> 2, cc = (l & 3) * 2;
        const int sr = nf * 8 + g_;
        const int wrow = (sr >> 4) * HID + j0 + (sr & 15);
        const size_t base = (size_t)wrow * HID + kt * 16 + cc;
        sWfH[(size_t)i * 2 + 0] = *reinterpret_cast<const unsigned *>(&g_Whh_hi[base]);
        sWfH[(size_t)i * 2 + 1] = *reinterpret_cast<const unsigned *>(&g_Whh_hi[base + 8]);
        sWfL[(size_t)i * 2 + 0] = *reinterpret_cast<const unsigned *>(&g_Whh_lo[base]);
        sWfL[(size_t)i * 2 + 1] = *reinterpret_cast<const unsigned *>(&g_Whh_lo[base + 8]);
    }

    // ---- epilogue mapping + bias preload ----
    const int er = tid >> 1;            // batch row 0..127
    const int u0 = (tid & 1) * 8;       // unit half
    float bsr[8], bsz[8], bin[8], bhn[8];
#pragma unroll
    for (int uu = 0; uu < 8; uu++) {
        const int j = j0 + u0 + uu;
        bsr[uu] = b_ih[j] + b_hh[j];
        bsz[uu] = b_ih[HID + j] + b_hh[HID + j];
        bin[uu] = b_ih[2 * HID + j];
        bhn[uu] = b_hh[2 * HID + j];
    }
    const size_t hoff = (size_t)(b0 + er) * HID + j0 + u0;   // linear fp32 h offset
    // fragment-store base for the epilogue
    const int m_w   = bt * 8 + (er >> 4);
    const int rr    = er & 15;
    const int wIdx  = ((rr >= 8) ? 1 : 0) + ((u0 >> 3) << 1);
    const size_t fragW = ((size_t)(m_w * 64 + ut) * 32 + (rr & 7) * 4) * 4 + wIdx;
    __syncthreads();

    // this warp's two M-fragments and K-range
    const int m0f = bt * 8 + mq * 2;
    const int kt0 = kh * 32;
    const size_t aidx0 = ((size_t)(m0f + 0) * 64) * 32 + lane;   // + ktg*32
    const size_t aidx1 = ((size_t)(m0f + 1) * 64) * 32 + lane;

    for (int t = 0; t < SEQ; t++) {
        const int rp = t & 1, wp = rp ^ 1;
        const uint4 *AH = reinterpret_cast<const uint4 *>(g_hfh[rp]);
        const uint4 *AL = reinterpret_cast<const uint4 *>(g_hfl[rp]);

        // ---- prefetch E-gather rows + h_prev for epilogue ----
        const int v = inputs[(b0 + er) * SEQ + t];
        const float *Er = &g_E[(size_t)v * G3 + j0 + u0];
        float4 exr0 = *reinterpret_cast<const float4 *>(Er);
        float4 exr1 = *reinterpret_cast<const float4 *>(Er + 4);
        float4 exz0 = *reinterpret_cast<const float4 *>(Er + HID);
        float4 exz1 = *reinterpret_cast<const float4 *>(Er + HID + 4);
        float4 exn0 = *reinterpret_cast<const float4 *>(Er + 2 * HID);
        float4 exn1 = *reinterpret_cast<const float4 *>(Er + 2 * HID + 4);
        float4 hp0 = __ldcg(reinterpret_cast<const float4 *>(&g_hlin[rp][hoff]));
        float4 hp1 = __ldcg(reinterpret_cast<const float4 *>(&g_hlin[rp][hoff + 4]));

        float acc[2][6][4] = {};

        // ---- 4-slot, distance-3 pipelined K-loop over this warp's 32 kt ----
        uint4 pAh[4][2], pAl[4][2];
#pragma unroll
        for (int s = 0; s < 3; s++) {
            pAh[s][0] = __ldcg(AH + aidx0 + (size_t)(kt0 + s) * 32);
            pAh[s][1] = __ldcg(AH + aidx1 + (size_t)(kt0 + s) * 32);
            pAl[s][0] = __ldcg(AL + aidx0 + (size_t)(kt0 + s) * 32);
            pAl[s][1] = __ldcg(AL + aidx1 + (size_t)(kt0 + s) * 32);
        }

#pragma unroll 4
        for (int k = 0; k < 32; k++) {
            const int slot = k & 3;
            if (k + 3 < 32) {
                const int ns = (k + 3) & 3;
                pAh[ns][0] = __ldcg(AH + aidx0 + (size_t)(kt0 + k + 3) * 32);
                pAh[ns][1] = __ldcg(AH + aidx1 + (size_t)(kt0 + k + 3) * 32);
                pAl[ns][0] = __ldcg(AL + aidx0 + (size_t)(kt0 + k + 3) * 32);
                pAl[ns][1] = __ldcg(AL + aidx1 + (size_t)(kt0 + k + 3) * 32);
            }
            const int ktg = kt0 + k;
            uint2 bhv[6], blv[6];
            {
                const uint2 *Bh = reinterpret_cast<const uint2 *>(sWfH) + (size_t)ktg * 32 + lane;
                const uint2 *Bl = reinterpret_cast<const uint2 *>(sWfL) + (size_t)ktg * 32 + lane;
#pragma unroll
                for (int nf = 0; nf < 6; nf++) {
                    bhv[nf] = Bh[(size_t)nf * 2048];
                    blv[nf] = Bl[(size_t)nf * 2048];
                }
            }
            unsigned ah0[4] = {pAh[slot][0].x, pAh[slot][0].y, pAh[slot][0].z, pAh[slot][0].w};
            unsigned ah1[4] = {pAh[slot][1].x, pAh[slot][1].y, pAh[slot][1].z, pAh[slot][1].w};
            unsigned al0[4] = {pAl[slot][0].x, pAl[slot][0].y, pAl[slot][0].z, pAl[slot][0].w};
            unsigned al1[4] = {pAl[slot][1].x, pAl[slot][1].y, pAl[slot][1].z, pAl[slot][1].w};
#pragma unroll
            for (int nf = 0; nf < 6; nf++) {
                unsigned *bh = reinterpret_cast<unsigned *>(&bhv[nf]);
                mma16816(acc[0][nf], ah0, bh);
                mma16816(acc[1][nf], ah1, bh);
            }
#pragma unroll
            for (int nf = 0; nf < 6; nf++) {
                unsigned *bl = reinterpret_cast<unsigned *>(&blv[nf]);
                mma16816(acc[0][nf], ah0, bl);
                mma16816(acc[1][nf], ah1, bl);
            }
#pragma unroll
            for (int nf = 0; nf < 6; nf++) {
                unsigned *bh = reinterpret_cast<unsigned *>(&bhv[nf]);
                mma16816(acc[0][nf], al0, bh);
                mma16816(acc[1][nf], al1, bh);
            }
        }

        // ---- K-reduction: warps 4-7 (kh=1) dump partials; warps 0-3 add ----
        if (kh == 1) {
            float *dst = sHg + (size_t)(mq * 32 + lane) * XC_STRIDE;
            int idx = 0;
#pragma unroll
            for (int i = 0; i < 2; i++)
#pragma unroll
                for (int nf = 0; nf < 6; nf++)
#pragma unroll
                    for (int q = 0; q < 4; q++) dst[idx++] = acc[i][nf][q];
        }
        __syncthreads();
        if (kh == 0) {
            const float *src = sHg + (size_t)(mq * 32 + lane) * XC_STRIDE;
            int idx = 0;
#pragma unroll
            for (int i = 0; i < 2; i++)
#pragma unroll
                for (int nf = 0; nf < 6; nf++)
#pragma unroll
                    for (int q = 0; q < 4; q++) acc[i][nf][q] += src[idx++];
        }
        __syncthreads();
        if (kh == 0) {
#pragma unroll
            for (int i = 0; i < 2; i++)
#pragma unroll
                for (int nf = 0; nf < 6; nf++) {
                    const int r0  = (mq * 2 + i) * 16 + g;
                    const int col = nf * 8 + c2;
                    sHg[r0 * HG_STRIDE + col]           = acc[i][nf][0];
                    sHg[r0 * HG_STRIDE + col + 1]       = acc[i][nf][1];
                    sHg[(r0 + 8) * HG_STRIDE + col]     = acc[i][nf][2];
                    sHg[(r0 + 8) * HG_STRIDE + col + 1] = acc[i][nf][3];
                }
        }
        __syncthreads();

        // ---- fused gating + h update ----
        float ex_r[8] = {exr0.x, exr0.y, exr0.z, exr0.w, exr1.x, exr1.y, exr1.z, exr1.w};
        float ex_z[8] = {exz0.x, exz0.y, exz0.z, exz0.w, exz1.x, exz1.y, exz1.z, exz1.w};
        float ex_n[8] = {exn0.x, exn0.y, exn0.z, exn0.w, exn1.x, exn1.y, exn1.z, exn1.w};
        float hp[8]   = {hp0.x, hp0.y, hp0.z, hp0.w, hp1.x, hp1.y, hp1.z, hp1.w};
        float outv[8];
#pragma unroll
        for (int uu = 0; uu < 8; uu++) {
            const int u = u0 + uu;
            const float hr = sHg[er * HG_STRIDE + u];
            const float hz = sHg[er * HG_STRIDE + 16 + u];
            const float hn = sHg[er * HG_STRIDE + 32 + u];
            const float rg = sigf(ex_r[uu] + hr + bsr[uu]);
            const float zg = sigf(ex_z[uu] + hz + bsz[uu]);
            const float ng = tanhf(ex_n[uu] + bin[uu] + rg * (hn + bhn[uu]));
            outv[uu] = (1.0f - zg) * ng + zg * hp[uu];
        }
        // write new h: linear fp32 plane + fragment-major bf16 planes (write plane wp)
        __stcg(reinterpret_cast<float4 *>(&g_hlin[wp][hoff]),
               make_float4(outv[0], outv[1], outv[2], outv[3]));
        __stcg(reinterpret_cast<float4 *>(&g_hlin[wp][hoff + 4]),
               make_float4(outv[4], outv[5], outv[6], outv[7]));
        {
            unsigned *fH = g_hfh[wp] + fragW;
            unsigned *fL = g_hfl[wp] + fragW;
#pragma unroll
            for (int q = 0; q < 4; q++) {
                __nv_bfloat16 h0, h1, l0, l1;
                split2(outv[2 * q], h0, l0);
                split2(outv[2 * q + 1], h1, l1);
                __stcg(fH + (size_t)q * 4, pk(h0, h1));
                __stcg(fL + (size_t)q * 4, pk(l0, l1));
            }
        }

        grid_bar((unsigned)(t + 1));
    }
}

// ---------------- kernel: zero h planes + reset barrier state ----------------
__global__ void k_zero() {
    int i = blockIdx.x * blockDim.x + threadIdx.x;
    if (i < 16 * 64 * 32 * 4) {
        g_hfh[0][i] = 0u;
        g_hfl[0][i] = 0u;
    }
    if (i < BATCH * HID) g_hlin[0][i] = 0.0f;
    if (i == 0) { g_count = 0; g_phase = 0; }
}

// ---------------- kernel: out = h_final @ W_dense^T + b_dense ----------------
__global__ void k_dense(const float *__restrict__ Wd, const float *__restrict__ bd,
                        float *__restrict__ out) {
    const int gw   = (blockIdx.x * (blockDim.x >> 5)) + (threadIdx.x >> 5);
    const int lane = threadIdx.x & 31;
    if (gw >= BATCH * 2) return;
    const int b = gw >> 1, o = gw & 1;
    const float *h = g_hlin[0];   // t=511 (rp=1) wrote plane 0
    float s = 0.0f;
    for (int i = lane; i < HID; i += 32) s += h[b * HID + i] * Wd[o * HID + i];
#pragma unroll
    for (int off = 16; off > 0; off >>= 1) s += __shfl_xor_sync(0xFFFFFFFFu, s, off);
    if (lane == 0) out[b * 2 + o] = s + bd[o];
}

// ---------------- launch ----------------
extern "C" void kernel_launch(void *const *d_in, const int *in_sizes, int n_in,
                              void *d_out, int out_size) {
    const int   *inputs  = (const int *)d_in[0];
    const float *emb     = (const float *)d_in[1];
    const float *W_ih    = (const float *)d_in[2];
    const float *W_hh    = (const float *)d_in[3];
    const float *b_ih    = (const float *)d_in[4];
    const float *b_hh    = (const float *)d_in[5];
    const float *W_dense = (const float *)d_in[6];
    const float *b_dense = (const float *)d_in[7];
    float *out = (float *)d_out;

    cudaFuncSetAttribute(k_scan, cudaFuncAttributeMaxDynamicSharedMemorySize, SMEM_TOTAL);

    k_split<<<6144, 1024>>>(W_ih, W_hh);
    k_vocab<<<dim3(24, 250), 256>>>(emb);
    k_zero<<<256, 1024>>>();
    k_scan<<<NCTA, 256, SMEM_TOTAL>>>(inputs, b_ih, b_hh);
    k_dense<<<64, 256>>>(W_dense, b_dense, out);
}